// round 9
// baseline (speedup 1.0000x reference)
#include <cuda_runtime.h>

#define NB   8
#define NH   32
#define NW   32
#define NC   32
#define HO   30
#define WO   30
#define NF   64
#define NPOS (NB * HO * WO)   // 7200

// Exact prune threshold: >= max over filters of (max_k w - min_k w).
// Monotone-accumulated via atomicMax on float bits (ranges are >= 0).
// Never reset: stale value is either identical (same inputs) or larger,
// and the prune is exact for ANY T >= max_f range_f.
__device__ float g_T;

// 16 blocks x 128 threads; block handles 4 filters over all 288 k.
__global__ __launch_bounds__(128) void trop_T_kernel(const float* __restrict__ w) {
    int t   = threadIdx.x;
    int fl  = t & 3;                   // filter within block
    int seg = t >> 2;                  // 0..31, 9 k's each
    int f   = blockIdx.x * 4 + fl;
    int k0  = seg * 9;
    float wmax = -1e30f, wmin = 1e30f;
#pragma unroll
    for (int q = 0; q < 9; q++) {
        float v = w[(k0 + q) * NF + f];
        wmax = fmaxf(wmax, v);
        wmin = fminf(wmin, v);
    }
    // reduce across the 8 segs within the warp (seg bits = lane bits 2..4)
#pragma unroll
    for (int o = 4; o <= 16; o <<= 1) {
        wmax = fmaxf(wmax, __shfl_xor_sync(0xffffffffu, wmax, o));
        wmin = fminf(wmin, __shfl_xor_sync(0xffffffffu, wmin, o));
    }
    __shared__ float sx[4][4], sn[4][4];
    int wid = t >> 5, lane = t & 31;
    if (lane < 4) { sx[wid][lane] = wmax; sn[wid][lane] = wmin; }
    __syncthreads();
    if (t < 4) {
        float m = fmaxf(fmaxf(sx[0][t], sx[1][t]), fmaxf(sx[2][t], sx[3][t]));
        float n = fminf(fminf(sn[0][t], sn[1][t]), fminf(sn[2][t], sn[3][t]));
        atomicMax((unsigned*)&g_T, __float_as_uint(m - n));
    }
}

// Warp-autonomous: no smem, no __syncthreads. Warp = output position,
// lane = channel. 9 coalesced LDGs bring the window to registers.
__global__ __launch_bounds__(256) void trop_main_kernel(
    const float* __restrict__ x, const float* __restrict__ w,
    const float* __restrict__ bias, float* __restrict__ out) {

    int g    = blockIdx.x * 8 + (threadIdx.x >> 5);
    int lane = threadIdx.x & 31;

    int wo = g % WO;
    int r  = g / WO;
    int ho = r % HO;
    int b  = r / HO;

    float bias0 = bias[lane];          // independent early loads
    float bias1 = bias[lane + 32];
    float T = g_T;

    // Phase 1: 9 independent coalesced loads -> registers.
    const float* xp = x + (((b * NH + ho) * NW) + wo) * NC + lane;
    float v[9];
#pragma unroll
    for (int i = 0; i < 3; i++)
#pragma unroll
        for (int j = 0; j < 3; j++)
            v[i * 3 + j] = xp[i * (NW * NC) + j * NC];

    // Phase 2: depth-4 tree reduce in-thread, then interleaved butterfly.
    float a0 = fmaxf(v[0], v[1]), a1 = fmaxf(v[2], v[3]);
    float a2 = fmaxf(v[4], v[5]), a3 = fmaxf(v[6], v[7]);
    float n0 = fminf(v[0], v[1]), n1 = fminf(v[2], v[3]);
    float n2 = fminf(v[4], v[5]), n3 = fminf(v[6], v[7]);
    float mx = fmaxf(fmaxf(fmaxf(a0, a1), fmaxf(a2, a3)), v[8]);
    float mn = fminf(fminf(fminf(n0, n1), fminf(n2, n3)), v[8]);
#pragma unroll
    for (int o = 16; o; o >>= 1) {
        float sa = __shfl_xor_sync(0xffffffffu, mx, o);
        float sb = __shfl_xor_sync(0xffffffffu, mn, o);
        mx = fmaxf(mx, sa);
        mn = fminf(mn, sb);
    }

    float th_hi = mx - T;
    float th_lo = mn + T;

    // Phase 3a: all 18 ballots up front (independent -> latency overlapped).
    unsigned hi[9], lo[9];
#pragma unroll
    for (int cell = 0; cell < 9; cell++) {
        hi[cell] = __ballot_sync(0xffffffffu, v[cell] >= th_hi);
        lo[cell] = __ballot_sync(0xffffffffu, v[cell] <= th_lo);
    }

    // Phase 3b: iterate candidates; one uniform skip per cell covers both
    // sides. Set max/min is order-independent -> deterministic.
    float amax0 = -1e30f, amax1 = -1e30f;
    float amin0 =  1e30f, amin1 =  1e30f;
#pragma unroll
    for (int cell = 0; cell < 9; cell++) {
        if (hi[cell] | lo[cell]) {
            float val = v[cell];
            unsigned mmax = hi[cell];
            while (mmax) {
                int c = __ffs(mmax) - 1; mmax &= mmax - 1;
                float pv = __shfl_sync(0xffffffffu, val, c);
                const float* wr = w + (cell * 32 + c) * NF;
                amax0 = fmaxf(amax0, pv + wr[lane]);
                amax1 = fmaxf(amax1, pv + wr[lane + 32]);
            }
            unsigned mmin = lo[cell];
            while (mmin) {
                int c = __ffs(mmin) - 1; mmin &= mmin - 1;
                float pv = __shfl_sync(0xffffffffu, val, c);
                const float* wr = w + (cell * 32 + c) * NF;
                amin0 = fminf(amin0, pv + wr[lane]);
                amin1 = fminf(amin1, pv + wr[lane + 32]);
            }
        }
    }

    // Phase 4: combine + bias, coalesced store.
    out[g * NF + lane]      = amax0 - amin0 + bias0;
    out[g * NF + lane + 32] = amax1 - amin1 + bias1;
}

extern "C" void kernel_launch(void* const* d_in, const int* in_sizes, int n_in,
                              void* d_out, int out_size) {
    (void)in_sizes; (void)n_in; (void)out_size;
    const float* x    = (const float*)d_in[0];
    const float* w    = (const float*)d_in[1];
    const float* bias = (const float*)d_in[2];
    float* out = (float*)d_out;

    trop_T_kernel<<<16, 128>>>(w);
    trop_main_kernel<<<NPOS / 8, 256>>>(x, w, bias, out);
}

// round 10
// speedup vs baseline: 1.0022x; 1.0022x over previous
#include <cuda_runtime.h>

#define NB   8
#define NH   32
#define NW   32
#define NC   32
#define HO   30
#define WO   30
#define NF   64

// Exact prune threshold: >= max over filters of (max_k w - min_k w).
// Monotone atomicMax on float bits (ranges >= 0 -> bit-order = value-order).
// Never reset: for fixed inputs T is identical every launch, and the prune
// is exact for ANY T >= the true bound.
__device__ float g_T;
__device__ int   g_cnt;    // T partials completed (mod 16)
__device__ int   g_flag;   // sticky: g_T ready

// Single fused kernel. Grid 720 x 320. Blocks 0..15 additionally compute the
// T partials (4 filters each) before consuming T themselves.
__global__ __launch_bounds__(320) void trop_fused_kernel(
    const float* __restrict__ x, const float* __restrict__ w,
    const float* __restrict__ bias, float* __restrict__ out) {

    int bx = blockIdx.x;
    int wg = bx % 3;                 // wo group: cols wg*10 .. wg*10+11
    int ho = (bx / 3) % HO;
    int b  = bx / (3 * HO);

    __shared__ float s[3][12 * NC];  // 4608 B patch
    __shared__ float sTx[9][4], sTn[9][4];

    int t    = threadIdx.x;
    int wp   = t >> 5;
    int lane = t & 31;

    // Phase 1: contiguous float4 patch load (3 rows x 12 cols x 32 ch).
    if (t < 288) {
        int row = t / 96;
        int q   = t - row * 96;
        const float4* src = (const float4*)(x + ((b * NH + ho + row) * NW + wg * 10) * NC);
        ((float4*)s[row])[q] = src[q];
    }

    // T partials: blocks 0..15, threads 0..287. Thread covers filter
    // f = bx*4 + (t&3) over 4 k's; warp-shfl folds the 8 segs per warp.
    if (bx < 16 && t < 288) {
        int fl  = t & 3;
        int seg = t >> 2;            // 0..71
        int f   = bx * 4 + fl;
        float wmax = -1e30f, wmin = 1e30f;
#pragma unroll
        for (int q = 0; q < 4; q++) {
            float v = w[(seg * 4 + q) * NF + f];
            wmax = fmaxf(wmax, v);
            wmin = fminf(wmin, v);
        }
#pragma unroll
        for (int o = 4; o <= 16; o <<= 1) {
            wmax = fmaxf(wmax, __shfl_xor_sync(0xffffffffu, wmax, o));
            wmin = fminf(wmin, __shfl_xor_sync(0xffffffffu, wmin, o));
        }
        if (lane < 4) { sTx[wp][lane] = wmax; sTn[wp][lane] = wmin; }
    }
    __syncthreads();

    // Finalize this block's 4-filter partial and publish.
    if (bx < 16 && t == 0) {
        float r = -1e30f;
#pragma unroll
        for (int fl = 0; fl < 4; fl++) {
            float m = -1e30f, n = 1e30f;
#pragma unroll
            for (int q = 0; q < 9; q++) {
                m = fmaxf(m, sTx[q][fl]);
                n = fminf(n, sTn[q][fl]);
            }
            r = fmaxf(r, m - n);
        }
        atomicMax((unsigned*)&g_T, __float_as_uint(r));
        __threadfence();
        if ((atomicAdd(&g_cnt, 1) & 15) == 15) {
            __threadfence();
            atomicExch(&g_flag, 1);
        }
    }

    int wo = wg * 10 + wp;

    // Phase 2: 9 window values in registers; interleaved SHFL butterfly.
    float v[9];
    float mx = -1e30f, mn = 1e30f;
#pragma unroll
    for (int i = 0; i < 3; i++)
#pragma unroll
        for (int j = 0; j < 3; j++) {
            float val = s[i][(wp + j) * NC + lane];
            v[i * 3 + j] = val;
            mx = fmaxf(mx, val);
            mn = fminf(mn, val);
        }
#pragma unroll
    for (int o = 16; o; o >>= 1) {
        float a  = __shfl_xor_sync(0xffffffffu, mx, o);
        float bq = __shfl_xor_sync(0xffffffffu, mn, o);
        mx = fmaxf(mx, a);
        mn = fminf(mn, bq);
    }

    // Gate: wait until T is published (first launch only; flag is sticky and
    // T is monotone -> identical value and output on every launch).
    if (lane == 0) {
        while (*(volatile int*)&g_flag == 0) { }
    }
    __syncwarp();
    __threadfence();
    float T = *(volatile float*)&g_T;

    // Phase 3: exact prune. k with p_k < max_p - T cannot achieve the
    // per-filter max for ANY filter (sym. min). Ballot + bit-iterate;
    // set max/min is order-independent -> deterministic.
    float th_hi = mx - T;
    float th_lo = mn + T;

    float amax0 = -1e30f, amax1 = -1e30f;
    float amin0 =  1e30f, amin1 =  1e30f;

#pragma unroll
    for (int cell = 0; cell < 9; cell++) {
        float val = v[cell];
        unsigned mmax = __ballot_sync(0xffffffffu, val >= th_hi);
        unsigned mmin = __ballot_sync(0xffffffffu, val <= th_lo);
        while (mmax) {
            int c = __ffs(mmax) - 1; mmax &= mmax - 1;
            float pv = __shfl_sync(0xffffffffu, val, c);
            const float* wr = w + (cell * 32 + c) * NF;
            amax0 = fmaxf(amax0, pv + wr[lane]);
            amax1 = fmaxf(amax1, pv + wr[lane + 32]);
        }
        while (mmin) {
            int c = __ffs(mmin) - 1; mmin &= mmin - 1;
            float pv = __shfl_sync(0xffffffffu, val, c);
            const float* wr = w + (cell * 32 + c) * NF;
            amin0 = fminf(amin0, pv + wr[lane]);
            amin1 = fminf(amin1, pv + wr[lane + 32]);
        }
    }

    // Phase 4: combine + bias, coalesced store.
    int pos = (b * HO + ho) * WO + wo;
    out[pos * NF + lane]      = amax0 - amin0 + bias[lane];
    out[pos * NF + lane + 32] = amax1 - amin1 + bias[lane + 32];
}

extern "C" void kernel_launch(void* const* d_in, const int* in_sizes, int n_in,
                              void* d_out, int out_size) {
    (void)in_sizes; (void)n_in; (void)out_size;
    const float* x    = (const float*)d_in[0];
    const float* w    = (const float*)d_in[1];
    const float* bias = (const float*)d_in[2];
    float* out = (float*)d_out;

    trop_fused_kernel<<<NB * HO * 3, 320>>>(x, w, bias, out);
}

// round 12
// speedup vs baseline: 1.3528x; 1.3499x over previous
#include <cuda_runtime.h>

#define NB   8
#define NH   32
#define NW   32
#define NC   32
#define HO   30
#define WO   30
#define NF   64
#define NK   288   // 3*3*32

// Exact prune threshold: max over filters of (max_k w - min_k w).
__device__ float g_T;

// Order-preserving float<->int key (involution, monotonic for non-NaN).
__device__ __forceinline__ int f2key(float x) {
    int b = __float_as_int(x);
    return b ^ ((b >> 31) & 0x7fffffff);
}
__device__ __forceinline__ float key2f(int k) {
    return __int_as_float(k ^ ((k >> 31) & 0x7fffffff));
}

// 1024 threads: 16 k-chunks x 64 filters, 18 independent L2 loads each.
__global__ __launch_bounds__(1024) void trop_T_kernel(const float* __restrict__ w) {
    __shared__ float smax[16][64];
    __shared__ float smin[16][64];
    int t = threadIdx.x;
    int f = t & 63;
    int chunk = t >> 6;
    int k0 = chunk * 18;
    float wmax = -1e30f, wmin = 1e30f;
#pragma unroll
    for (int q = 0; q < 18; q++) {
        float v = w[(k0 + q) * NF + f];
        wmax = fmaxf(wmax, v);
        wmin = fminf(wmin, v);
    }
    smax[chunk][f] = wmax;
    smin[chunk][f] = wmin;
    __syncthreads();
    if (t < 32) {
        float a0 = -1e30f, b0 = 1e30f, a1 = -1e30f, b1 = 1e30f;
#pragma unroll
        for (int q = 0; q < 16; q++) {
            a0 = fmaxf(a0, smax[q][t]);      b0 = fminf(b0, smin[q][t]);
            a1 = fmaxf(a1, smax[q][t + 32]); b1 = fminf(b1, smin[q][t + 32]);
        }
        int r = __reduce_max_sync(0xffffffffu, f2key(fmaxf(a0 - b0, a1 - b1)));
        if (t == 0) g_T = key2f(r);
    }
}

// Block = (b, ho, wgroup of 10 wo). 320 threads = 10 warps, warp = position,
// lane = channel.
__global__ __launch_bounds__(320) void trop_main_kernel(
    const float* __restrict__ x, const float* __restrict__ w,
    const float* __restrict__ bias, float* __restrict__ out) {

    int bx = blockIdx.x;
    int wg = bx % 3;
    int ho = (bx / 3) % HO;
    int b  = bx / (3 * HO);

    __shared__ float s[3][12 * NC];           // 4608 B patch

    int t    = threadIdx.x;
    int wp   = t >> 5;
    int lane = t & 31;

    // Independent early loads (latency hidden under the patch-load chain).
    float T     = g_T;
    float bias0 = bias[lane];
    float bias1 = bias[lane + 32];

    // Phase 1: contiguous float4 patch load (3 rows x 12 cols x 32 ch).
    if (t < 288) {
        int row = t / 96;
        int q   = t - row * 96;
        const float4* src = (const float4*)(x + ((b * NH + ho + row) * NW + wg * 10) * NC);
        ((float4*)s[row])[q] = src[q];
    }
    __syncthreads();

    int wo = wg * 10 + wp;

    // Phase 2: 9 window values in registers; int-key accumulate + REDUX
    // (s32 redux exists on sm_103; fp32 does not).
    float v[9];
    int kmx = 0x80000000, kmn = 0x7fffffff;
#pragma unroll
    for (int i = 0; i < 3; i++)
#pragma unroll
        for (int j = 0; j < 3; j++) {
            float val = s[i][(wp + j) * NC + lane];
            v[i * 3 + j] = val;
            int kb = f2key(val);
            kmx = max(kmx, kb);
            kmn = min(kmn, kb);
        }
    kmx = __reduce_max_sync(0xffffffffu, kmx);
    kmn = __reduce_min_sync(0xffffffffu, kmn);
    float mx = key2f(kmx);
    float mn = key2f(kmn);

    // Phase 3: exact prune. k with p_k < max_p - T cannot achieve the
    // per-filter max for ANY filter (sym. min). Ballot + bit-iterate;
    // set max/min is order-independent -> deterministic.
    float th_hi = mx - T;
    float th_lo = mn + T;

    float amax0 = -1e30f, amax1 = -1e30f;
    float amin0 =  1e30f, amin1 =  1e30f;

#pragma unroll
    for (int cell = 0; cell < 9; cell++) {
        float val = v[cell];
        unsigned mmax = __ballot_sync(0xffffffffu, val >= th_hi);
        unsigned mmin = __ballot_sync(0xffffffffu, val <= th_lo);
        while (mmax) {
            int c = __ffs(mmax) - 1; mmax &= mmax - 1;
            float pv = __shfl_sync(0xffffffffu, val, c);
            const float* wr = w + (cell * 32 + c) * NF;
            amax0 = fmaxf(amax0, pv + wr[lane]);
            amax1 = fmaxf(amax1, pv + wr[lane + 32]);
        }
        while (mmin) {
            int c = __ffs(mmin) - 1; mmin &= mmin - 1;
            float pv = __shfl_sync(0xffffffffu, val, c);
            const float* wr = w + (cell * 32 + c) * NF;
            amin0 = fminf(amin0, pv + wr[lane]);
            amin1 = fminf(amin1, pv + wr[lane + 32]);
        }
    }

    // Phase 4: combine + bias, coalesced store.
    int pos = (b * HO + ho) * WO + wo;
    out[pos * NF + lane]      = amax0 - amin0 + bias0;
    out[pos * NF + lane + 32] = amax1 - amin1 + bias1;
}

extern "C" void kernel_launch(void* const* d_in, const int* in_sizes, int n_in,
                              void* d_out, int out_size) {
    (void)in_sizes; (void)n_in; (void)out_size;
    const float* x    = (const float*)d_in[0];
    const float* w    = (const float*)d_in[1];
    const float* bias = (const float*)d_in[2];
    float* out = (float*)d_out;

    trop_T_kernel<<<1, 1024>>>(w);
    trop_main_kernel<<<NB * HO * 3, 320>>>(x, w, bias, out);
}

// round 13
// speedup vs baseline: 1.3851x; 1.0239x over previous
#include <cuda_runtime.h>

#define NB   8
#define NH   32
#define NW   32
#define NC   32
#define HO   30
#define WO   30
#define NF   64
#define NK   288   // 3*3*32

// Exact prune threshold: max over filters of (max_k w - min_k w).
__device__ float g_T;

// Order-preserving float<->int key (monotonic for non-NaN).
__device__ __forceinline__ int f2key(float x) {
    int b = __float_as_int(x);
    return b ^ ((b >> 31) & 0x7fffffff);
}
__device__ __forceinline__ float key2f(int k) {
    return __int_as_float(k ^ ((k >> 31) & 0x7fffffff));
}

// 1024 threads: 16 k-chunks x 64 filters, 18 independent L2 loads each.
// Fires launch_dependents at entry so the main grid launches concurrently.
__global__ __launch_bounds__(1024) void trop_T_kernel(const float* __restrict__ w) {
    asm volatile("griddepcontrol.launch_dependents;" ::: "memory");
    __shared__ float smax[16][64];
    __shared__ float smin[16][64];
    int t = threadIdx.x;
    int f = t & 63;
    int chunk = t >> 6;
    int k0 = chunk * 18;
    float wmax = -1e30f, wmin = 1e30f;
#pragma unroll
    for (int q = 0; q < 18; q++) {
        float v = w[(k0 + q) * NF + f];
        wmax = fmaxf(wmax, v);
        wmin = fminf(wmin, v);
    }
    smax[chunk][f] = wmax;
    smin[chunk][f] = wmin;
    __syncthreads();
    if (t < 32) {
        float a0 = -1e30f, b0 = 1e30f, a1 = -1e30f, b1 = 1e30f;
#pragma unroll
        for (int q = 0; q < 16; q++) {
            a0 = fmaxf(a0, smax[q][t]);      b0 = fminf(b0, smin[q][t]);
            a1 = fmaxf(a1, smax[q][t + 32]); b1 = fminf(b1, smin[q][t + 32]);
        }
        int r = __reduce_max_sync(0xffffffffu, f2key(fmaxf(a0 - b0, a1 - b1)));
        if (t == 0) g_T = key2f(r);
    }
}

// Block = (b, ho, wgroup of 10 wo). 320 threads = 10 warps, warp = position,
// lane = channel. PDL: runs concurrently with trop_T_kernel until the
// griddepcontrol.wait below.
__global__ __launch_bounds__(320) void trop_main_kernel(
    const float* __restrict__ x, const float* __restrict__ w,
    const float* __restrict__ bias, float* __restrict__ out) {

    int bx = blockIdx.x;
    int wg = bx % 3;
    int ho = (bx / 3) % HO;
    int b  = bx / (3 * HO);

    __shared__ float s[3][12 * NC];           // 4608 B patch

    int t    = threadIdx.x;
    int wp   = t >> 5;
    int lane = t & 31;

    float bias0 = bias[lane];
    float bias1 = bias[lane + 32];

    // Phase 1: contiguous float4 patch load (3 rows x 12 cols x 32 ch).
    if (t < 288) {
        int row = t / 96;
        int q   = t - row * 96;
        const float4* src = (const float4*)(x + ((b * NH + ho + row) * NW + wg * 10) * NC);
        ((float4*)s[row])[q] = src[q];
    }
    __syncthreads();

    int wo = wg * 10 + wp;

    // Phase 2: 9 window values in registers; interleaved SHFL butterfly.
    float v[9];
    float mx = -1e30f, mn = 1e30f;
#pragma unroll
    for (int i = 0; i < 3; i++)
#pragma unroll
        for (int j = 0; j < 3; j++) {
            float val = s[i][(wp + j) * NC + lane];
            v[i * 3 + j] = val;
            mx = fmaxf(mx, val);
            mn = fminf(mn, val);
        }
#pragma unroll
    for (int o = 16; o; o >>= 1) {
        float a  = __shfl_xor_sync(0xffffffffu, mx, o);
        float bq = __shfl_xor_sync(0xffffffffu, mn, o);
        mx = fmaxf(mx, a);
        mn = fminf(mn, bq);
    }

    // PDL gate: T kernel is complete (and its writes visible) after this.
    asm volatile("griddepcontrol.wait;" ::: "memory");
    float T = g_T;

    // Phase 3: exact prune. k with p_k < max_p - T cannot achieve the
    // per-filter max for ANY filter (sym. min). Ballot + bit-iterate;
    // set max/min is order-independent -> deterministic.
    float th_hi = mx - T;
    float th_lo = mn + T;

    float amax0 = -1e30f, amax1 = -1e30f;
    float amin0 =  1e30f, amin1 =  1e30f;

#pragma unroll
    for (int cell = 0; cell < 9; cell++) {
        float val = v[cell];
        unsigned mmax = __ballot_sync(0xffffffffu, val >= th_hi);
        unsigned mmin = __ballot_sync(0xffffffffu, val <= th_lo);
        while (mmax) {
            int c = __ffs(mmax) - 1; mmax &= mmax - 1;
            float pv = __shfl_sync(0xffffffffu, val, c);
            const float* wr = w + (cell * 32 + c) * NF;
            amax0 = fmaxf(amax0, pv + wr[lane]);
            amax1 = fmaxf(amax1, pv + wr[lane + 32]);
        }
        while (mmin) {
            int c = __ffs(mmin) - 1; mmin &= mmin - 1;
            float pv = __shfl_sync(0xffffffffu, val, c);
            const float* wr = w + (cell * 32 + c) * NF;
            amin0 = fminf(amin0, pv + wr[lane]);
            amin1 = fminf(amin1, pv + wr[lane + 32]);
        }
    }

    // Phase 4: combine + bias, coalesced store.
    int pos = (b * HO + ho) * WO + wo;
    out[pos * NF + lane]      = amax0 - amin0 + bias0;
    out[pos * NF + lane + 32] = amax1 - amin1 + bias1;
}

extern "C" void kernel_launch(void* const* d_in, const int* in_sizes, int n_in,
                              void* d_out, int out_size) {
    (void)in_sizes; (void)n_in; (void)out_size;
    const float* x    = (const float*)d_in[0];
    const float* w    = (const float*)d_in[1];
    const float* bias = (const float*)d_in[2];
    float* out = (float*)d_out;

    trop_T_kernel<<<1, 1024>>>(w);

    cudaLaunchConfig_t cfg = {};
    cfg.gridDim  = dim3(NB * HO * 3);
    cfg.blockDim = dim3(320);
    cfg.stream   = 0;  // legacy default stream (same as <<<>>> above)
    cudaLaunchAttribute attr[1];
    attr[0].id = cudaLaunchAttributeProgrammaticStreamSerialization;
    attr[0].val.programmaticStreamSerializationAllowed = 1;
    cfg.attrs    = attr;
    cfg.numAttrs = 1;
    cudaLaunchKernelEx(&cfg, trop_main_kernel, x, w, bias, out);
}